// round 14
// baseline (speedup 1.0000x reference)
#include <cuda_runtime.h>
#include <cuda_fp16.h>
#include <cstdint>

#define N_NODES 50000
#define N_EDGES 800000
#define DIM 128
#define SCAN_NB ((N_NODES + 255) / 256)   // 196 blocks

// Scratch (device globals)
__device__ int    g_cnt[N_NODES];
__device__ int    g_off[N_NODES + 1];
__device__ int    g_cur[N_NODES];
__device__ int    g_bsum[SCAN_NB];
__device__ float  g_dinv[N_NODES];
__device__ int2   g_edge[N_EDGES];        // {src, norm bits} CSR-by-dst order
__device__ __half g_tmph[N_NODES * DIM];  // GEMM output, fp16 (all gather reads)
__device__ float  g_h[N_NODES * DIM];     // layer-1 aggregated output fp32

// ---------------- degree / CSR build ----------------
__global__ void k_zero_cnt() {
    int i = blockIdx.x * blockDim.x + threadIdx.x;
    if (i < N_NODES) g_cnt[i] = 0;
}

__global__ void k_hist(const int* __restrict__ ei) {
    int e = blockIdx.x * blockDim.x + threadIdx.x;
    if (e < N_EDGES) atomicAdd(&g_cnt[ei[N_EDGES + e]], 1);
}

// scan phase 1 + dinv fused (warp-shuffle scan)
__global__ void k_scan1() {
    __shared__ int ws[8];
    int tid = threadIdx.x;
    int lane = tid & 31, w = tid >> 5;
    int i = blockIdx.x * 256 + tid;
    int v = (i < N_NODES) ? g_cnt[i] : 0;
    if (i < N_NODES) g_dinv[i] = rsqrtf((float)(v + 1));   // +1 self-loop

    int x = v;
#pragma unroll
    for (int d = 1; d < 32; d <<= 1) {
        int t = __shfl_up_sync(0xffffffffu, x, d);
        if (lane >= d) x += t;
    }
    if (lane == 31) ws[w] = x;
    __syncthreads();
    if (w == 0) {
        int s = (lane < 8) ? ws[lane] : 0;
#pragma unroll
        for (int d = 1; d < 8; d <<= 1) {
            int t = __shfl_up_sync(0xffffffffu, s, d);
            if (lane >= d) s += t;
        }
        if (lane < 8) ws[lane] = s;
    }
    __syncthreads();
    int base = (w > 0) ? ws[w - 1] : 0;
    if (i < N_NODES) g_off[i] = base + x - v;          // exclusive local
    if (tid == 255) g_bsum[blockIdx.x] = ws[7];
}

// scan phase 2: per-block redundant reduction of global offset (shuffle reduce)
__global__ void k_scan3() {
    __shared__ int red[8];
    int b = blockIdx.x;
    int t = threadIdx.x;
    int lane = t & 31, w = t >> 5;
    int partial = 0;
    for (int j = t; j < b; j += 256) partial += g_bsum[j];
#pragma unroll
    for (int d = 16; d > 0; d >>= 1)
        partial += __shfl_down_sync(0xffffffffu, partial, d);
    if (lane == 0) red[w] = partial;
    __syncthreads();
    if (w == 0) {
        int s = (lane < 8) ? red[lane] : 0;
#pragma unroll
        for (int d = 4; d > 0; d >>= 1)
            s += __shfl_down_sync(0xffffffffu, s, d);
        if (lane == 0) red[0] = s;
    }
    __syncthreads();
    int boff = red[0];
    int i = b * 256 + t;
    if (i < N_NODES) {
        int o = g_off[i] + boff;
        g_off[i] = o;
        g_cur[i] = o;
    }
    if (i == 0) g_off[N_NODES] = N_EDGES;
}

__global__ void k_scatter(const int* __restrict__ ei) {
    int e = blockIdx.x * blockDim.x + threadIdx.x;
    if (e >= N_EDGES) return;
    int src = ei[e];
    int dst = ei[N_EDGES + e];
    int pos = atomicAdd(&g_cur[dst], 1);
    float norm = g_dinv[src] * g_dinv[dst];
    g_edge[pos] = make_int2(src, __float_as_int(norm));
}

// ---------------- fp16 HMMA GEMM: OutH = fp16(act(X) @ W) ----------------
__device__ __forceinline__ uint32_t smem_u32(const void* p) {
    return (uint32_t)__cvta_generic_to_shared(p);
}
__device__ __forceinline__ void ldsm_x4(uint32_t addr, uint32_t& r0, uint32_t& r1,
                                        uint32_t& r2, uint32_t& r3) {
    asm volatile("ldmatrix.sync.aligned.m8n8.x4.shared.b16 {%0,%1,%2,%3},[%4];"
        : "=r"(r0), "=r"(r1), "=r"(r2), "=r"(r3) : "r"(addr));
}
__device__ __forceinline__ void ldsm_x4_t(uint32_t addr, uint32_t& r0, uint32_t& r1,
                                          uint32_t& r2, uint32_t& r3) {
    asm volatile("ldmatrix.sync.aligned.m8n8.x4.trans.shared.b16 {%0,%1,%2,%3},[%4];"
        : "=r"(r0), "=r"(r1), "=r"(r2), "=r"(r3) : "r"(addr));
}
__device__ __forceinline__ void mma_f16(float* d, const uint32_t* a, uint32_t b0, uint32_t b1) {
    asm volatile("mma.sync.aligned.m16n8k16.row.col.f32.f16.f16.f32 "
        "{%0,%1,%2,%3},{%4,%5,%6,%7},{%8,%9},{%0,%1,%2,%3};"
        : "+f"(d[0]), "+f"(d[1]), "+f"(d[2]), "+f"(d[3])
        : "r"(a[0]), "r"(a[1]), "r"(a[2]), "r"(a[3]), "r"(b0), "r"(b1));
}

#define XS 72
#define WS 136

template<bool RELU>
__global__ void __launch_bounds__(256, 2)
k_gemm(const float* __restrict__ X, const float* __restrict__ W,
       __half* __restrict__ OutH) {
    __shared__ __align__(16) __half sX[128 * XS];
    __shared__ __align__(16) __half sW[64 * WS];

    int tid  = threadIdx.x;
    int warp = tid >> 5;
    int lane = tid & 31;
    int g    = lane >> 2, tg = lane & 3;
    int row0 = blockIdx.x * 128;
    int R0 = (warp & 3) * 32;
    int C0 = (warp >> 2) * 64;

    float acc[2][8][4];
#pragma unroll
    for (int mf = 0; mf < 2; mf++)
#pragma unroll
        for (int nf = 0; nf < 8; nf++)
#pragma unroll
            for (int c = 0; c < 4; c++) acc[mf][nf][c] = 0.f;

    int lr = lane & 15, lc = lane >> 4;

    for (int kk = 0; kk < DIM; kk += 64) {
#pragma unroll
        for (int i = 0; i < 8; i++) {
            int idx = i * 256 + tid;
            int r = idx >> 4, c4 = (idx & 15) * 4;
            int row = row0 + r;
            float4 v = make_float4(0.f, 0.f, 0.f, 0.f);
            if (row < N_NODES) v = *(const float4*)&X[row * DIM + kk + c4];
            if (RELU) {
                v.x = fmaxf(v.x, 0.f); v.y = fmaxf(v.y, 0.f);
                v.z = fmaxf(v.z, 0.f); v.w = fmaxf(v.w, 0.f);
            }
            *(__half2*)&sX[r * XS + c4 + 0] = __floats2half2_rn(v.x, v.y);
            *(__half2*)&sX[r * XS + c4 + 2] = __floats2half2_rn(v.z, v.w);
        }
#pragma unroll
        for (int i = 0; i < 8; i++) {
            int idx = i * 256 + tid;
            int k = idx >> 5, c4 = (idx & 31) * 4;
            float4 v = *(const float4*)&W[(kk + k) * DIM + c4];
            *(__half2*)&sW[k * WS + c4 + 0] = __floats2half2_rn(v.x, v.y);
            *(__half2*)&sW[k * WS + c4 + 2] = __floats2half2_rn(v.z, v.w);
        }
        __syncthreads();

#pragma unroll
        for (int ks = 0; ks < 4; ks++) {
            uint32_t a0[4], a1[4];
            ldsm_x4(smem_u32(&sX[(R0 + lr) * XS + ks * 16 + lc * 8]),
                    a0[0], a0[1], a0[2], a0[3]);
            ldsm_x4(smem_u32(&sX[(R0 + 16 + lr) * XS + ks * 16 + lc * 8]),
                    a1[0], a1[1], a1[2], a1[3]);
#pragma unroll
            for (int np = 0; np < 4; np++) {
                uint32_t b0, b1, b2, b3;
                ldsm_x4_t(smem_u32(&sW[(ks * 16 + lr) * WS + C0 + np * 16 + lc * 8]),
                          b0, b1, b2, b3);
                mma_f16(acc[0][2 * np],     a0, b0, b1);
                mma_f16(acc[1][2 * np],     a1, b0, b1);
                mma_f16(acc[0][2 * np + 1], a0, b2, b3);
                mma_f16(acc[1][2 * np + 1], a1, b2, b3);
            }
        }
        __syncthreads();
    }

#pragma unroll
    for (int mf = 0; mf < 2; mf++) {
        int r_lo = row0 + R0 + mf * 16 + g;
        int r_hi = r_lo + 8;
#pragma unroll
        for (int nf = 0; nf < 8; nf++) {
            int col = C0 + nf * 8 + 2 * tg;
            float* d = acc[mf][nf];
            if (r_lo < N_NODES)
                *(__half2*)&OutH[r_lo * DIM + col] = __floats2half2_rn(d[0], d[1]);
            if (r_hi < N_NODES)
                *(__half2*)&OutH[r_hi * DIM + col] = __floats2half2_rn(d[2], d[3]);
        }
    }
}

// ---------------- CSR gather aggregation (all-fp16 source rows) ----------------
__device__ __forceinline__ void acc_half(float4& acc, uint2 p, float n) {
    float2 lo = __half22float2(*(__half2*)&p.x);
    float2 hi = __half22float2(*(__half2*)&p.y);
    acc.x += lo.x * n; acc.y += lo.y * n;
    acc.z += hi.x * n; acc.w += hi.y * n;
}

__global__ void k_gather(const __half* __restrict__ tmph,
                         const float* __restrict__ bias, float* __restrict__ out) {
    int node = (int)((blockIdx.x * (unsigned)blockDim.x + threadIdx.x) >> 5);
    int lane = threadIdx.x & 31;
    if (node >= N_NODES) return;

    int beg = g_off[node];
    int end = g_off[node + 1];
    float dd = g_dinv[node];
    float self = dd * dd;

    float4 acc = make_float4(0.f, 0.f, 0.f, 0.f);
    uint2 ps = *(const uint2*)&tmph[node * DIM + lane * 4];
    acc_half(acc, ps, self);

    int e = beg;
    for (; e + 3 < end; e += 4) {
        int2 m0 = g_edge[e + 0];
        int2 m1 = g_edge[e + 1];
        int2 m2 = g_edge[e + 2];
        int2 m3 = g_edge[e + 3];
        uint2 p0 = *(const uint2*)&tmph[m0.x * DIM + lane * 4];
        uint2 p1 = *(const uint2*)&tmph[m1.x * DIM + lane * 4];
        uint2 p2 = *(const uint2*)&tmph[m2.x * DIM + lane * 4];
        uint2 p3 = *(const uint2*)&tmph[m3.x * DIM + lane * 4];
        acc_half(acc, p0, __int_as_float(m0.y));
        acc_half(acc, p1, __int_as_float(m1.y));
        acc_half(acc, p2, __int_as_float(m2.y));
        acc_half(acc, p3, __int_as_float(m3.y));
    }
    for (; e < end; e++) {
        int2 m0 = g_edge[e];
        uint2 p0 = *(const uint2*)&tmph[m0.x * DIM + lane * 4];
        acc_half(acc, p0, __int_as_float(m0.y));
    }

    float4 bb = *(const float4*)&bias[lane * 4];
    acc.x += bb.x; acc.y += bb.y; acc.z += bb.z; acc.w += bb.w;
    *(float4*)&out[node * DIM + lane * 4] = acc;
}

// ---------------- launch ----------------
extern "C" void kernel_launch(void* const* d_in, const int* in_sizes, int n_in,
                              void* d_out, int out_size) {
    const float* x  = (const float*)d_in[0];
    const int*   ei = (const int*)d_in[1];
    const float* W1 = (const float*)d_in[2];
    const float* b1 = (const float*)d_in[3];
    const float* W2 = (const float*)d_in[4];
    const float* b2 = (const float*)d_in[5];
    float* out = (float*)d_out;

    __half* tmph_p; cudaGetSymbolAddress((void**)&tmph_p, g_tmph);
    float*  h_p;    cudaGetSymbolAddress((void**)&h_p,    g_h);

    int nthr = 256;
    int nb_nodes  = (N_NODES + nthr - 1) / nthr;
    int nb_edges  = (N_EDGES + nthr - 1) / nthr;
    int nb_gemm   = (N_NODES + 127) / 128;
    int nb_gather = (N_NODES * 32 + nthr - 1) / nthr;

    // Side stream: gemm1 overlaps the CSR build (proven win; keep).
    cudaStream_t s2;
    cudaStreamCreateWithFlags(&s2, cudaStreamNonBlocking);
    cudaEvent_t evFork, evJoin;
    cudaEventCreateWithFlags(&evFork, cudaEventDisableTiming);
    cudaEventCreateWithFlags(&evJoin, cudaEventDisableTiming);

    cudaEventRecord(evFork, 0);
    cudaStreamWaitEvent(s2, evFork, 0);
    k_gemm<false><<<nb_gemm, nthr, 0, s2>>>(x, W1, tmph_p);
    cudaEventRecord(evJoin, s2);

    // CSR build chain (concurrent with gemm1)
    k_zero_cnt<<<nb_nodes, nthr>>>();
    k_hist<<<nb_edges, nthr>>>(ei);
    k_scan1<<<SCAN_NB, 256>>>();
    k_scan3<<<SCAN_NB, 256>>>();
    k_scatter<<<nb_edges, nthr>>>(ei);

    cudaStreamWaitEvent(0, evJoin, 0);

    // layer 1 aggregation
    k_gather<<<nb_gather, nthr>>>(tmph_p, b1, h_p);

    // layer 2 (serial — chunked pipelining measured slower)
    k_gemm<true><<<nb_gemm, nthr>>>(h_p, W2, tmph_p);
    k_gather<<<nb_gather, nthr>>>(tmph_p, b2, out);
}

// round 16
// speedup vs baseline: 1.2627x; 1.2627x over previous
#include <cuda_runtime.h>
#include <cuda_fp16.h>
#include <cstdint>

#define N_NODES 50000
#define N_EDGES 800000
#define DIM 128
#define SCAN_NB ((N_NODES + 255) / 256)   // 196 blocks

// Scratch (device globals)
__device__ int    g_cnt[N_NODES];
__device__ int    g_off[N_NODES + 1];
__device__ int    g_cur[N_NODES];
__device__ int    g_bsum[SCAN_NB];
__device__ float  g_dinv[N_NODES];
__device__ int2   g_edge[N_EDGES];        // {src, norm bits} CSR-by-dst order
__device__ float  g_tmp[N_NODES * DIM];   // GEMM output fp32
__device__ __half g_tmph[N_NODES * DIM];  // GEMM output fp16 mirror (gather neighbor reads)
__device__ float  g_h[N_NODES * DIM];

// ---------------- degree / CSR build ----------------
__global__ void k_zero_cnt() {
    int i = blockIdx.x * blockDim.x + threadIdx.x;
    if (i < N_NODES) g_cnt[i] = 0;
}

__global__ void k_hist(const int* __restrict__ ei) {
    int e = blockIdx.x * blockDim.x + threadIdx.x;
    if (e < N_EDGES) atomicAdd(&g_cnt[ei[N_EDGES + e]], 1);
}

__global__ void k_scan1() {
    __shared__ int s[256];
    int tid = threadIdx.x;
    int i = blockIdx.x * 256 + tid;
    int v = (i < N_NODES) ? g_cnt[i] : 0;
    if (i < N_NODES) g_dinv[i] = rsqrtf((float)(v + 1));   // +1 self-loop
    s[tid] = v;
    __syncthreads();
#pragma unroll
    for (int d = 1; d < 256; d <<= 1) {
        int t = (tid >= d) ? s[tid - d] : 0;
        __syncthreads();
        s[tid] += t;
        __syncthreads();
    }
    if (i < N_NODES) g_off[i] = s[tid] - v;
    if (tid == 255) g_bsum[blockIdx.x] = s[255];
}

__global__ void k_scan3() {
    __shared__ int red[256];
    int b = blockIdx.x;
    int t = threadIdx.x;
    int partial = 0;
    for (int j = t; j < b; j += 256) partial += g_bsum[j];
    red[t] = partial;
    __syncthreads();
#pragma unroll
    for (int d = 128; d > 0; d >>= 1) {
        if (t < d) red[t] += red[t + d];
        __syncthreads();
    }
    int boff = red[0];
    int i = b * 256 + t;
    if (i < N_NODES) {
        int o = g_off[i] + boff;
        g_off[i] = o;
        g_cur[i] = o;
    }
    if (i == 0) g_off[N_NODES] = N_EDGES;
}

__global__ void k_scatter(const int* __restrict__ ei) {
    int e = blockIdx.x * blockDim.x + threadIdx.x;
    if (e >= N_EDGES) return;
    int src = ei[e];
    int dst = ei[N_EDGES + e];
    int pos = atomicAdd(&g_cur[dst], 1);
    float norm = g_dinv[src] * g_dinv[dst];
    g_edge[pos] = make_int2(src, __float_as_int(norm));
}

// ---------------- fp16 HMMA GEMM: Out = act(X) @ W ----------------
__device__ __forceinline__ uint32_t smem_u32(const void* p) {
    return (uint32_t)__cvta_generic_to_shared(p);
}
__device__ __forceinline__ void ldsm_x4(uint32_t addr, uint32_t& r0, uint32_t& r1,
                                        uint32_t& r2, uint32_t& r3) {
    asm volatile("ldmatrix.sync.aligned.m8n8.x4.shared.b16 {%0,%1,%2,%3},[%4];"
        : "=r"(r0), "=r"(r1), "=r"(r2), "=r"(r3) : "r"(addr));
}
__device__ __forceinline__ void ldsm_x4_t(uint32_t addr, uint32_t& r0, uint32_t& r1,
                                          uint32_t& r2, uint32_t& r3) {
    asm volatile("ldmatrix.sync.aligned.m8n8.x4.trans.shared.b16 {%0,%1,%2,%3},[%4];"
        : "=r"(r0), "=r"(r1), "=r"(r2), "=r"(r3) : "r"(addr));
}
__device__ __forceinline__ void mma_f16(float* d, const uint32_t* a, uint32_t b0, uint32_t b1) {
    asm volatile("mma.sync.aligned.m16n8k16.row.col.f32.f16.f16.f32 "
        "{%0,%1,%2,%3},{%4,%5,%6,%7},{%8,%9},{%0,%1,%2,%3};"
        : "+f"(d[0]), "+f"(d[1]), "+f"(d[2]), "+f"(d[3])
        : "r"(a[0]), "r"(a[1]), "r"(a[2]), "r"(a[3]), "r"(b0), "r"(b1));
}

#define XS 72    // sX stride (halves): ldmatrix conflict-free
#define WS 136   // sW stride (halves): ldmatrix conflict-free

template<bool RELU>
__global__ void __launch_bounds__(256, 2)
k_gemm(const float* __restrict__ X, const float* __restrict__ W,
       float* __restrict__ Out, __half* __restrict__ OutH) {
    __shared__ __align__(16) __half sX[128 * XS];   // [m 0..127][k 0..63]
    __shared__ __align__(16) __half sW[64 * WS];    // [k 0..63][n 0..127]

    int tid  = threadIdx.x;
    int warp = tid >> 5;
    int lane = tid & 31;
    int g    = lane >> 2, tg = lane & 3;
    int row0 = blockIdx.x * 128;
    int R0 = (warp & 3) * 32;     // warp row group (32 rows)
    int C0 = (warp >> 2) * 64;    // warp col group (64 cols)

    float acc[2][8][4];
#pragma unroll
    for (int mf = 0; mf < 2; mf++)
#pragma unroll
        for (int nf = 0; nf < 8; nf++)
#pragma unroll
            for (int c = 0; c < 4; c++) acc[mf][nf][c] = 0.f;

    int lr = lane & 15, lc = lane >> 4;   // ldmatrix lane mapping

    for (int kk = 0; kk < DIM; kk += 64) {
        // fill X chunk: 128 rows x 64 k  (8 float4 per thread)
#pragma unroll
        for (int i = 0; i < 8; i++) {
            int idx = i * 256 + tid;
            int r = idx >> 4, c4 = (idx & 15) * 4;
            int row = row0 + r;
            float4 v = make_float4(0.f, 0.f, 0.f, 0.f);
            if (row < N_NODES) v = *(const float4*)&X[row * DIM + kk + c4];
            if (RELU) {
                v.x = fmaxf(v.x, 0.f); v.y = fmaxf(v.y, 0.f);
                v.z = fmaxf(v.z, 0.f); v.w = fmaxf(v.w, 0.f);
            }
            __half2 h0 = __floats2half2_rn(v.x, v.y);
            __half2 h1 = __floats2half2_rn(v.z, v.w);
            *(__half2*)&sX[r * XS + c4 + 0] = h0;
            *(__half2*)&sX[r * XS + c4 + 2] = h1;
        }
        // fill W chunk: 64 k x 128 n
#pragma unroll
        for (int i = 0; i < 8; i++) {
            int idx = i * 256 + tid;
            int k = idx >> 5, c4 = (idx & 31) * 4;
            float4 v = *(const float4*)&W[(kk + k) * DIM + c4];
            __half2 h0 = __floats2half2_rn(v.x, v.y);
            __half2 h1 = __floats2half2_rn(v.z, v.w);
            *(__half2*)&sW[k * WS + c4 + 0] = h0;
            *(__half2*)&sW[k * WS + c4 + 2] = h1;
        }
        __syncthreads();

#pragma unroll
        for (int ks = 0; ks < 4; ks++) {
            uint32_t a0[4], a1[4];
            ldsm_x4(smem_u32(&sX[(R0 + lr) * XS + ks * 16 + lc * 8]),
                    a0[0], a0[1], a0[2], a0[3]);
            ldsm_x4(smem_u32(&sX[(R0 + 16 + lr) * XS + ks * 16 + lc * 8]),
                    a1[0], a1[1], a1[2], a1[3]);
#pragma unroll
            for (int np = 0; np < 4; np++) {
                uint32_t b0, b1, b2, b3;
                ldsm_x4_t(smem_u32(&sW[(ks * 16 + lr) * WS + C0 + np * 16 + lc * 8]),
                          b0, b1, b2, b3);
                mma_f16(acc[0][2 * np],     a0, b0, b1);
                mma_f16(acc[1][2 * np],     a1, b0, b1);
                mma_f16(acc[0][2 * np + 1], a0, b2, b3);
                mma_f16(acc[1][2 * np + 1], a1, b2, b3);
            }
        }
        __syncthreads();
    }

    // epilogue: fp32 + fp16 mirror
#pragma unroll
    for (int mf = 0; mf < 2; mf++) {
        int r_lo = row0 + R0 + mf * 16 + g;
        int r_hi = r_lo + 8;
#pragma unroll
        for (int nf = 0; nf < 8; nf++) {
            int col = C0 + nf * 8 + 2 * tg;
            float* d = acc[mf][nf];
            if (r_lo < N_NODES) {
                *(float2*)&Out[r_lo * DIM + col] = make_float2(d[0], d[1]);
                *(__half2*)&OutH[r_lo * DIM + col] = __floats2half2_rn(d[0], d[1]);
            }
            if (r_hi < N_NODES) {
                *(float2*)&Out[r_hi * DIM + col] = make_float2(d[2], d[3]);
                *(__half2*)&OutH[r_hi * DIM + col] = __floats2half2_rn(d[2], d[3]);
            }
        }
    }
}

// ---------------- CSR gather aggregation ----------------
__device__ __forceinline__ void acc_half(float4& acc, uint2 p, float n) {
    float2 lo = __half22float2(*(__half2*)&p.x);
    float2 hi = __half22float2(*(__half2*)&p.y);
    acc.x += lo.x * n; acc.y += lo.y * n;
    acc.z += hi.x * n; acc.w += hi.y * n;
}

__global__ void k_gather(const float* __restrict__ tmp, const __half* __restrict__ tmph,
                         const float* __restrict__ bias, float* __restrict__ out) {
    int node = (int)((blockIdx.x * (unsigned)blockDim.x + threadIdx.x) >> 5);
    int lane = threadIdx.x & 31;
    if (node >= N_NODES) return;

    int beg = g_off[node];
    int end = g_off[node + 1];
    float dd = g_dinv[node];
    float self = dd * dd;

    float4 v = *(const float4*)&tmp[node * DIM + lane * 4];
    float4 acc = make_float4(v.x * self, v.y * self, v.z * self, v.w * self);

    int e = beg;
    // unroll 8: raise MLP to cover L2 latency
    for (; e + 7 < end; e += 8) {
        int2 m[8];
        uint2 p[8];
#pragma unroll
        for (int j = 0; j < 8; j++) m[j] = g_edge[e + j];
#pragma unroll
        for (int j = 0; j < 8; j++) p[j] = *(const uint2*)&tmph[m[j].x * DIM + lane * 4];
#pragma unroll
        for (int j = 0; j < 8; j++) acc_half(acc, p[j], __int_as_float(m[j].y));
    }
    for (; e + 3 < end; e += 4) {
        int2 m0 = g_edge[e + 0];
        int2 m1 = g_edge[e + 1];
        int2 m2 = g_edge[e + 2];
        int2 m3 = g_edge[e + 3];
        uint2 p0 = *(const uint2*)&tmph[m0.x * DIM + lane * 4];
        uint2 p1 = *(const uint2*)&tmph[m1.x * DIM + lane * 4];
        uint2 p2 = *(const uint2*)&tmph[m2.x * DIM + lane * 4];
        uint2 p3 = *(const uint2*)&tmph[m3.x * DIM + lane * 4];
        acc_half(acc, p0, __int_as_float(m0.y));
        acc_half(acc, p1, __int_as_float(m1.y));
        acc_half(acc, p2, __int_as_float(m2.y));
        acc_half(acc, p3, __int_as_float(m3.y));
    }
    for (; e < end; e++) {
        int2 m0 = g_edge[e];
        uint2 p0 = *(const uint2*)&tmph[m0.x * DIM + lane * 4];
        acc_half(acc, p0, __int_as_float(m0.y));
    }

    float4 bb = *(const float4*)&bias[lane * 4];
    acc.x += bb.x; acc.y += bb.y; acc.z += bb.z; acc.w += bb.w;
    *(float4*)&out[node * DIM + lane * 4] = acc;
}

// ---------------- launch ----------------
extern "C" void kernel_launch(void* const* d_in, const int* in_sizes, int n_in,
                              void* d_out, int out_size) {
    const float* x  = (const float*)d_in[0];
    const int*   ei = (const int*)d_in[1];
    const float* W1 = (const float*)d_in[2];
    const float* b1 = (const float*)d_in[3];
    const float* W2 = (const float*)d_in[4];
    const float* b2 = (const float*)d_in[5];
    float* out = (float*)d_out;

    float*  tmp_p;  cudaGetSymbolAddress((void**)&tmp_p,  g_tmp);
    __half* tmph_p; cudaGetSymbolAddress((void**)&tmph_p, g_tmph);
    float*  h_p;    cudaGetSymbolAddress((void**)&h_p,    g_h);

    int nthr = 256;
    int nb_nodes  = (N_NODES + nthr - 1) / nthr;
    int nb_edges  = (N_EDGES + nthr - 1) / nthr;
    int nb_gemm   = (N_NODES + 127) / 128;
    int nb_gather = (N_NODES * 32 + nthr - 1) / nthr;

    // Side stream: gemm1 overlaps the CSR build.
    cudaStream_t s2;
    cudaStreamCreateWithFlags(&s2, cudaStreamNonBlocking);
    cudaEvent_t evFork, evJoin;
    cudaEventCreateWithFlags(&evFork, cudaEventDisableTiming);
    cudaEventCreateWithFlags(&evJoin, cudaEventDisableTiming);

    cudaEventRecord(evFork, 0);
    cudaStreamWaitEvent(s2, evFork, 0);
    k_gemm<false><<<nb_gemm, nthr, 0, s2>>>(x, W1, tmp_p, tmph_p);
    cudaEventRecord(evJoin, s2);

    // CSR build chain (concurrent with gemm1)
    k_zero_cnt<<<nb_nodes, nthr>>>();
    k_hist<<<nb_edges, nthr>>>(ei);
    k_scan1<<<SCAN_NB, 256>>>();
    k_scan3<<<SCAN_NB, 256>>>();
    k_scatter<<<nb_edges, nthr>>>(ei);

    cudaStreamWaitEvent(0, evJoin, 0);

    // layer 1 aggregation
    k_gather<<<nb_gather, nthr>>>(tmp_p, tmph_p, b1, h_p);

    // layer 2
    k_gemm<true><<<nb_gemm, nthr>>>(h_p, W2, tmp_p, tmph_p);
    k_gather<<<nb_gather, nthr>>>(tmp_p, tmph_p, b2, out);
}